// round 13
// baseline (speedup 1.0000x reference)
#include <cuda_runtime.h>
#include <cuda_bf16.h>
#include <stdint.h>

// Problem constants (fixed by the dataset)
#define N_STAGES 100
#define N_TREES  3
#define TREE_DEPTH 6
#define N_INT    63
#define N_LEAF   64                     // tables padded to 64 slots/tree
#define NF       32
#define LR       0.1f

#define BLOCK    512                    // rows per block; grid 294 = balanced wave
#define NCH      10                     // ILP-10 independent chains
#define GSTAGES  (N_STAGES / NCH)       // 10 stages per chain
#define SLOTS    (N_STAGES * N_LEAF)    // 6400 node slots (one tree-column)
#define CHUNK    128                    // rows per transpose chunk

// ---- SMEM per CTA: 108,032 B -> 2 CTAs/SM (32 warps) ----
// node_s: u32[6400]    packed node = ikey(thr) rounded so low5 == feature;
//                      depth-d window <=32 consecutive u32 -> conflict-free
// xs    : u32[32*512]  ikey(x) transposed; stride 512%32==0 -> bank == lane
// xtmp  : f32[128*33]  bounce buffer for coalesced-LDG transpose
#define OFF_NODE 0
#define OFF_XS   (SLOTS * 4)                       // 25600
#define OFF_XT   (OFF_XS + NF * BLOCK * 4)         // 91136
#define SMEM_BYTES (OFF_XT + CHUNK * 33 * 4)       // 108032

// Monotone total-order key: x > t  <=>  ikey(x) > ikey(t)  (unsigned)
__device__ __forceinline__ uint32_t f32_ikey(uint32_t b) {
    return b ^ ((uint32_t)((int32_t)b >> 31) | 0x80000000u);
}

__global__ __launch_bounds__(BLOCK, 2)
void gbt_kernel(const float* __restrict__ x,
                const int*   __restrict__ feat,
                const float* __restrict__ thr,
                const float* __restrict__ lv,
                const float* __restrict__ init_pred,
                float* __restrict__ out,
                int N)
{
    extern __shared__ unsigned char sm[];
    uint32_t* node_s = reinterpret_cast<uint32_t*>(sm + OFF_NODE);
    uint32_t* xs     = reinterpret_cast<uint32_t*>(sm + OFF_XS);
    float*    xtmp   = reinterpret_cast<float*>(sm + OFF_XT);

    const int tid = threadIdx.x;
    const int rb  = blockIdx.x / N_TREES;        // row-block id (0..97)
    const int tr  = blockIdx.x - rb * N_TREES;   // tree column (class) 0..2
    const int rowBase = rb * BLOCK;

    // ---- Stage packed node words (pad each tree to 64 slots) ----
    // w = nearest key to ikey(thr) whose low 5 bits == feature (<=16 ulp perturb)
    #pragma unroll 4
    for (int k = tid; k < SLOTS; k += BLOCK) {
        int s = k >> 6, i = k & 63;              // stage, node-in-tree
        uint32_t w = 0;
        if (i < N_INT) {
            int g = (s * N_TREES + tr) * N_INT + i;
            uint32_t ik = f32_ikey(__float_as_uint(__ldg(thr + g)));
            uint32_t f  = (uint32_t)__ldg(feat + g);
            uint32_t cand = (ik & ~31u) | f;
            int32_t delta = (int32_t)(ik - cand);
            if (delta > 16)       cand += 32u;
            else if (delta < -16) cand -= 32u;
            w = cand;
        }
        node_s[k] = w;
    }

    // ---- Stage x transposed via SMEM bounce; convert to ikey in phase 2 ----
    for (int c0 = 0; c0 < BLOCK; c0 += CHUNK) {
        #pragma unroll
        for (int k = tid; k < CHUNK * NF; k += BLOCK) {   // coalesced LDG
            int r = k >> 5, f = k & 31;
            int row = rowBase + c0 + r;
            xtmp[r * 33 + f] = (row < N) ? __ldg(x + row * NF + f) : 0.0f;
        }
        __syncthreads();
        #pragma unroll
        for (int k = tid; k < CHUNK * NF; k += BLOCK) {   // conflict-free both sides
            int f = k / CHUNK, rr = k & (CHUNK - 1);
            xs[f * BLOCK + c0 + rr] =
                f32_ikey(__float_as_uint(xtmp[rr * 33 + f]));
        }
        __syncthreads();
    }

    const int row = rowBase + tid;
    if (row >= N) return;                        // no further block syncs

    const char* __restrict__ xb = reinterpret_cast<const char*>(xs) + tid * 4;

    float acc0 = 0.0f, acc1 = 0.0f;

    // Uniform per-stage pointers (block-uniform -> UR candidates):
    //   nb  = node words for stage s, chain c at immediate offset c*640 words
    //   lvs = leaf base: global leaf = s*192 + tr*64 + (b-63), b in [63,126]
    const uint32_t* nb  = node_s;
    const float*    lvs = lv + tr * N_LEAF - N_INT;

    #pragma unroll 2
    for (int s = 0; s < GSTAGES; ++s) {
        // NCH chains at stages s, s+10, ..., s+90; relative heap index b:
        // b' = 2b + 1 + p  (immediate +1 -> ISETP + IADD3.X, no K register)
        int b[NCH];
        #pragma unroll
        for (int c = 0; c < NCH; ++c) b[c] = 0;

        #pragma unroll
        for (int d = 0; d < TREE_DEPTH; ++d) {
            uint32_t w[NCH], xv[NCH];
            #pragma unroll
            for (int c = 0; c < NCH; ++c)
                w[c] = nb[b[c] + c * (GSTAGES * N_LEAF)];   // imm offset c*640
            #pragma unroll
            for (int c = 0; c < NCH; ++c)
                xv[c] = *reinterpret_cast<const uint32_t*>(
                            xb + (w[c] & 31u) * (BLOCK * 4));
            #pragma unroll
            for (int c = 0; c < NCH; ++c)
                b[c] = b[c] + b[c] + 1 + ((xv[c] > w[c]) ? 1 : 0);
        }
        #pragma unroll
        for (int c = 0; c < NCH; c += 2) {
            acc0 += __ldg(lvs + c       * (GSTAGES * N_TREES * N_LEAF) + b[c]);
            acc1 += __ldg(lvs + (c + 1) * (GSTAGES * N_TREES * N_LEAF) + b[c + 1]);
        }
        nb  += N_LEAF;                  // next stage's node block (64 words)
        lvs += N_TREES * N_LEAF;        // next stage's leaf block (192 floats)
    }

    out[row * N_TREES + tr] = __ldg(init_pred + tr) + LR * (acc0 + acc1);
}

extern "C" void kernel_launch(void* const* d_in, const int* in_sizes, int n_in,
                              void* d_out, int out_size)
{
    const float* x    = (const float*)d_in[0];   // [N, 32] f32
    const int*   feat = (const int*)  d_in[1];   // [100, 3, 63] i32
    const float* thr  = (const float*)d_in[2];   // [100, 3, 63] f32
    const float* lv   = (const float*)d_in[3];   // [100, 3, 64] f32
    const float* ip   = (const float*)d_in[4];   // [3] f32
    float* out = (float*)d_out;                  // [N, 3] f32

    const int N = in_sizes[0] / NF;

    cudaFuncSetAttribute(gbt_kernel,
                         cudaFuncAttributeMaxDynamicSharedMemorySize, SMEM_BYTES);

    const int rowBlocks = (N + BLOCK - 1) / BLOCK;       // 98
    const int grid = rowBlocks * N_TREES;                // 294 -> one wave @ 2 CTA/SM
    gbt_kernel<<<grid, BLOCK, SMEM_BYTES>>>(x, feat, thr, lv, ip, out, N);
}

// round 14
// speedup vs baseline: 1.1617x; 1.1617x over previous
#include <cuda_runtime.h>
#include <cuda_bf16.h>
#include <stdint.h>

// Problem constants (fixed by the dataset)
#define N_STAGES 100
#define N_TREES  3
#define TREE_DEPTH 6
#define N_INT    63
#define N_LEAF   64                     // tables padded to 64 slots/tree
#define NF       32
#define LR       0.1f

#define BLOCK    512                    // rows per block; grid 294 = balanced wave
#define NCH      10                     // ILP-10 independent chains
#define GSTAGES  (N_STAGES / NCH)       // 10 stages per chain
#define SLOTS    (N_STAGES * N_LEAF)    // 6400 node slots (one tree-column)
#define CHUNK    64                     // rows per transpose chunk

// ---- SMEM per CTA: 99,584 B -> 2 CTAs/SM (32 warps) ----
// node_s: u32[6400]   packed node = ikey(thr) rounded so low5 == feature;
//                     depth-d window <=32 consecutive u32 -> conflict-free
// xs    : u32[32*512] ikey(x) transposed; stride 512%32==0 -> bank == lane
// xtmp  : f32[64*33]  bounce buffer for coalesced-LDG transpose
#define OFF_NODE 0
#define OFF_XS   (SLOTS * 4)                       // 25600
#define OFF_XT   (OFF_XS + NF * BLOCK * 4)         // 91136
#define SMEM_BYTES (OFF_XT + CHUNK * 33 * 4)       // 99584

// Monotone total-order key: x > t  <=>  ikey(x) > ikey(t)  (unsigned)
__device__ __forceinline__ uint32_t f32_ikey(uint32_t b) {
    return b ^ ((uint32_t)((int32_t)b >> 31) | 0x80000000u);
}

__global__ __launch_bounds__(BLOCK, 2)
void gbt_kernel(const float* __restrict__ x,
                const int*   __restrict__ feat,
                const float* __restrict__ thr,
                const float* __restrict__ lv,
                const float* __restrict__ init_pred,
                float* __restrict__ out,
                int N)
{
    extern __shared__ unsigned char sm[];
    uint32_t* node_s = reinterpret_cast<uint32_t*>(sm + OFF_NODE);
    uint32_t* xs     = reinterpret_cast<uint32_t*>(sm + OFF_XS);
    float*    xtmp   = reinterpret_cast<float*>(sm + OFF_XT);

    const int tid = threadIdx.x;
    const int rb  = blockIdx.x / N_TREES;        // row-block id (0..97)
    const int tr  = blockIdx.x - rb * N_TREES;   // tree column (class) 0..2
    const int rowBase = rb * BLOCK;

    // ---- Stage packed node words (pad each tree to 64 slots) ----
    // w = nearest key to ikey(thr) whose low 5 bits == feature (<=16 ulp perturb)
    #pragma unroll 4
    for (int k = tid; k < SLOTS; k += BLOCK) {
        int s = k >> 6, i = k & 63;              // stage, node-in-tree
        uint32_t w = 0;
        if (i < N_INT) {
            int g = (s * N_TREES + tr) * N_INT + i;
            uint32_t ik = f32_ikey(__float_as_uint(__ldg(thr + g)));
            uint32_t f  = (uint32_t)__ldg(feat + g);
            uint32_t cand = (ik & ~31u) | f;
            int32_t delta = (int32_t)(ik - cand);
            if (delta > 16)       cand += 32u;
            else if (delta < -16) cand -= 32u;
            w = cand;
        }
        node_s[k] = w;
    }

    // ---- Stage x transposed via SMEM bounce; convert to ikey in phase 2 ----
    for (int c0 = 0; c0 < BLOCK; c0 += CHUNK) {
        #pragma unroll
        for (int k = tid; k < CHUNK * NF; k += BLOCK) {   // coalesced LDG
            int r = k >> 5, f = k & 31;
            int row = rowBase + c0 + r;
            xtmp[r * 33 + f] = (row < N) ? __ldg(x + row * NF + f) : 0.0f;
        }
        __syncthreads();
        #pragma unroll
        for (int k = tid; k < CHUNK * NF; k += BLOCK) {   // conflict-free both sides
            int f = k >> 6, rr = k & 63;
            xs[f * BLOCK + c0 + rr] =
                f32_ikey(__float_as_uint(xtmp[rr * 33 + f]));
        }
        __syncthreads();
    }

    const int row = rowBase + tid;
    if (row >= N) return;                        // no further block syncs

    const char* __restrict__ xb = reinterpret_cast<const char*>(xs) + tid * 4;
    // Leaf identity: a = s*64 + leaf_in_tree + 63 embeds s*64, so
    // global leaf = s*192 + tr*64 + leaf_in_tree = 128*s + (tr*64 - 63) + a.
    const float* __restrict__ lvt = lv + tr * N_LEAF - N_INT;

    float acc0 = 0.0f, acc1 = 0.0f;   // 2 accumulators instead of 10: frees 8 regs

    #pragma unroll 1
    for (int s = 0; s < GSTAGES; ++s) {
        // NCH independent traversal chains: stages s, s+10, s+20, ..., s+90
        int a[NCH];
        int K[NCH];
        #pragma unroll
        for (int c = 0; c < NCH; ++c) {
            a[c] = (s + c * GSTAGES) * N_LEAF;
            K[c] = 1 - a[c];                     // slot' = 2*slot + K + pred
        }
        #pragma unroll
        for (int d = 0; d < TREE_DEPTH; ++d) {
            uint32_t w[NCH], xv[NCH];
            #pragma unroll
            for (int c = 0; c < NCH; ++c) w[c] = node_s[a[c]];
            #pragma unroll
            for (int c = 0; c < NCH; ++c)
                xv[c] = *reinterpret_cast<const uint32_t*>(
                            xb + (w[c] & 31u) * (BLOCK * 4));
            #pragma unroll
            for (int c = 0; c < NCH; ++c)
                a[c] = a[c] + a[c] + K[c] + ((xv[c] > w[c]) ? 1 : 0);
        }
        #pragma unroll
        for (int c = 0; c < NCH; c += 2) {
            acc0 += __ldg(lvt + 128 * (s +  c      * GSTAGES) + a[c]);
            acc1 += __ldg(lvt + 128 * (s + (c + 1) * GSTAGES) + a[c + 1]);
        }
    }

    out[row * N_TREES + tr] = __ldg(init_pred + tr) + LR * (acc0 + acc1);
}

extern "C" void kernel_launch(void* const* d_in, const int* in_sizes, int n_in,
                              void* d_out, int out_size)
{
    const float* x    = (const float*)d_in[0];   // [N, 32] f32
    const int*   feat = (const int*)  d_in[1];   // [100, 3, 63] i32
    const float* thr  = (const float*)d_in[2];   // [100, 3, 63] f32
    const float* lv   = (const float*)d_in[3];   // [100, 3, 64] f32
    const float* ip   = (const float*)d_in[4];   // [3] f32
    float* out = (float*)d_out;                  // [N, 3] f32

    const int N = in_sizes[0] / NF;

    cudaFuncSetAttribute(gbt_kernel,
                         cudaFuncAttributeMaxDynamicSharedMemorySize, SMEM_BYTES);

    const int rowBlocks = (N + BLOCK - 1) / BLOCK;       // 98
    const int grid = rowBlocks * N_TREES;                // 294 -> one wave @ 2 CTA/SM
    gbt_kernel<<<grid, BLOCK, SMEM_BYTES>>>(x, feat, thr, lv, ip, out, N);
}

// round 15
// speedup vs baseline: 1.1626x; 1.0008x over previous
#include <cuda_runtime.h>
#include <cuda_bf16.h>
#include <stdint.h>

// Problem constants (fixed by the dataset)
#define N_STAGES 100
#define N_TREES  3
#define TREE_DEPTH 6
#define N_INT    63
#define N_LEAF   64                     // tables padded to 64 slots/tree
#define NF       32
#define LR       0.1f

#define BLOCK    512                    // rows per block; grid 294 = balanced wave
#define NCH      10                     // ILP-10 independent chains
#define GSTAGES  (N_STAGES / NCH)       // 10 stages per chain
#define SLOTS    (N_STAGES * N_LEAF)    // 6400 node slots (one tree-column)
#define CHUNK    128                    // rows per transpose chunk (xtmp 16.9KB)

// ---- SMEM per CTA: 89,600 B -> 2 CTAs/SM, L1D grows to ~49KB (leaf-resident)
// node_s: u32[6400]    packed node = ikey(thr) rounded so low5 == feature;
//                      depth-d window <=32 consecutive u32 -> conflict-free
// xs    : u32[32*512]  ikey(x) transposed; stride 512%32==0 -> bank == lane
// xtmp  : f32[128*33]  ALIASES node_s (transpose runs before node staging)
#define OFF_NODE 0
#define OFF_XS   (SLOTS * 4)                       // 25600
#define SMEM_BYTES (OFF_XS + NF * BLOCK * 4)       // 89600

// Monotone total-order key: x > t  <=>  ikey(x) > ikey(t)  (unsigned)
__device__ __forceinline__ uint32_t f32_ikey(uint32_t b) {
    return b ^ ((uint32_t)((int32_t)b >> 31) | 0x80000000u);
}

__global__ __launch_bounds__(BLOCK, 2)
void gbt_kernel(const float* __restrict__ x,
                const int*   __restrict__ feat,
                const float* __restrict__ thr,
                const float* __restrict__ lv,
                const float* __restrict__ init_pred,
                float* __restrict__ out,
                int N)
{
    extern __shared__ unsigned char sm[];
    uint32_t* node_s = reinterpret_cast<uint32_t*>(sm + OFF_NODE);
    uint32_t* xs     = reinterpret_cast<uint32_t*>(sm + OFF_XS);
    float*    xtmp   = reinterpret_cast<float*>(sm + OFF_NODE);  // alias over nodes

    const int tid = threadIdx.x;
    const int rb  = blockIdx.x / N_TREES;        // row-block id (0..97)
    const int tr  = blockIdx.x - rb * N_TREES;   // tree column (class) 0..2
    const int rowBase = rb * BLOCK;

    // ---- 1) Stage x transposed via aliased bounce buffer (4 chunks of 128) ----
    for (int c0 = 0; c0 < BLOCK; c0 += CHUNK) {
        // Phase 1: float4 coalesced global read -> xtmp row-major (stride 33).
        // STS banks: (33r + f4 + j) mod 32 = r + f4 + j, distinct per warp.
        #pragma unroll
        for (int it = 0; it < (CHUNK * NF / 4) / BLOCK; ++it) {   // 2 iters
            int kk = tid + it * BLOCK;
            int r  = kk >> 3;                    // 0..127
            int f4 = (kk & 7) * 4;
            int row = rowBase + c0 + r;
            float4 v = make_float4(0.f, 0.f, 0.f, 0.f);
            if (row < N)
                v = *reinterpret_cast<const float4*>(x + row * NF + f4);
            float* dst = xtmp + r * 33 + f4;
            dst[0] = v.x; dst[1] = v.y; dst[2] = v.z; dst[3] = v.w;
        }
        __syncthreads();
        // Phase 2: conflict-free SMEM transpose + ikey convert.
        // LDS bank = (rr + f) mod 32 (rr consecutive); STS bank = (c0+rr) mod 32.
        #pragma unroll
        for (int it = 0; it < (CHUNK * NF) / BLOCK; ++it) {       // 8 iters
            int k  = tid + it * BLOCK;
            int f  = k >> 7;                     // 0..31
            int rr = k & 127;
            xs[f * BLOCK + c0 + rr] =
                f32_ikey(__float_as_uint(xtmp[rr * 33 + f]));
        }
        __syncthreads();
    }

    // ---- 2) Stage packed node words (overwrites the aliased xtmp region) ----
    // w = nearest key to ikey(thr) whose low 5 bits == feature (<=16 ulp perturb)
    for (int k = tid; k < SLOTS; k += BLOCK) {
        int s = k >> 6, i = k & 63;              // stage, node-in-tree
        uint32_t w = 0;
        if (i < N_INT) {
            int g = (s * N_TREES + tr) * N_INT + i;
            uint32_t ik = f32_ikey(__float_as_uint(__ldg(thr + g)));
            uint32_t f  = (uint32_t)__ldg(feat + g);
            uint32_t cand = (ik & ~31u) | f;
            int32_t delta = (int32_t)(ik - cand);
            if (delta > 16)       cand += 32u;
            else if (delta < -16) cand -= 32u;
            w = cand;
        }
        node_s[k] = w;
    }
    __syncthreads();

    const int row = rowBase + tid;
    if (row >= N) return;                        // no further block syncs

    const char* __restrict__ xb = reinterpret_cast<const char*>(xs) + tid * 4;
    // Leaf identity: a = s*64 + leaf_in_tree + 63 embeds s*64, so
    // global leaf = s*192 + tr*64 + leaf_in_tree = 128*s + (tr*64 - 63) + a.
    const float* __restrict__ lvt = lv + tr * N_LEAF - N_INT;

    float acc0 = 0.0f, acc1 = 0.0f;

    #pragma unroll 1
    for (int s = 0; s < GSTAGES; ++s) {
        // NCH independent traversal chains: stages s, s+10, s+20, ..., s+90
        int a[NCH];
        int K[NCH];
        #pragma unroll
        for (int c = 0; c < NCH; ++c) {
            a[c] = (s + c * GSTAGES) * N_LEAF;
            K[c] = 1 - a[c];                     // slot' = 2*slot + K + pred
        }
        #pragma unroll
        for (int d = 0; d < TREE_DEPTH; ++d) {
            uint32_t w[NCH], xv[NCH];
            #pragma unroll
            for (int c = 0; c < NCH; ++c) w[c] = node_s[a[c]];
            #pragma unroll
            for (int c = 0; c < NCH; ++c)
                xv[c] = *reinterpret_cast<const uint32_t*>(
                            xb + (w[c] & 31u) * (BLOCK * 4));
            #pragma unroll
            for (int c = 0; c < NCH; ++c)
                a[c] = a[c] + a[c] + K[c] + ((xv[c] > w[c]) ? 1 : 0);
        }
        #pragma unroll
        for (int c = 0; c < NCH; c += 2) {
            acc0 += __ldg(lvt + 128 * (s +  c      * GSTAGES) + a[c]);
            acc1 += __ldg(lvt + 128 * (s + (c + 1) * GSTAGES) + a[c + 1]);
        }
    }

    out[row * N_TREES + tr] = __ldg(init_pred + tr) + LR * (acc0 + acc1);
}

extern "C" void kernel_launch(void* const* d_in, const int* in_sizes, int n_in,
                              void* d_out, int out_size)
{
    const float* x    = (const float*)d_in[0];   // [N, 32] f32
    const int*   feat = (const int*)  d_in[1];   // [100, 3, 63] i32
    const float* thr  = (const float*)d_in[2];   // [100, 3, 63] f32
    const float* lv   = (const float*)d_in[3];   // [100, 3, 64] f32
    const float* ip   = (const float*)d_in[4];   // [3] f32
    float* out = (float*)d_out;                  // [N, 3] f32

    const int N = in_sizes[0] / NF;

    cudaFuncSetAttribute(gbt_kernel,
                         cudaFuncAttributeMaxDynamicSharedMemorySize, SMEM_BYTES);

    const int rowBlocks = (N + BLOCK - 1) / BLOCK;       // 98
    const int grid = rowBlocks * N_TREES;                // 294 -> one wave @ 2 CTA/SM
    gbt_kernel<<<grid, BLOCK, SMEM_BYTES>>>(x, feat, thr, lv, ip, out, N);
}